// round 2
// baseline (speedup 1.0000x reference)
#include <cuda_runtime.h>
#include <stdint.h>

#define BATCH 32
#define NPTS  16384
#define NROT  24
#define IMS   64
#define NPIX  (IMS * IMS)
#define TOTPIX (BATCH * NROT * NPIX)   // 3,145,728

// 25 MB scratch: packed (n+1)<<32 | float_bits(val). Zero-initialized at module
// load; the unpack kernel resets it to zero every call so graph replays see a
// clean state.
__device__ unsigned long long g_scratch[TOTPIX];

__global__ __launch_bounds__(256) void scatter_kernel(
    const float* __restrict__ xyz, const float* __restrict__ rot)
{
    __shared__ float4 srot[NROT];   // (m00, m02, m20, m22) = (c, -s, s, c)
    int tid = threadIdx.x;
    if (tid < NROT) {
        const float* m = rot + tid * 9;
        srot[tid] = make_float4(m[0], m[2], m[6], m[8]);
    }
    __syncthreads();

    int p = blockIdx.x * 256 + tid;          // point index in [0, BATCH*NPTS)
    int b = p >> 14;
    int n = p & (NPTS - 1);

    float x = xyz[p * 3 + 0];
    float y = xyz[p * 3 + 1];
    float z = xyz[p * 3 + 2];

    // y' == y for all rotations -> py computed once.
    int py = (int)rintf((y + 2.0f) * 16.0f);
    bool py_in = (py >= 0) & (py < IMS);
    int py_off = py * IMS;

    unsigned long long tag = ((unsigned long long)(n + 1)) << 32;
    unsigned long long* base = g_scratch + (size_t)b * NROT * NPIX;

#pragma unroll
    for (int r = 0; r < NROT; r++) {
        float4 m = srot[r];
        // Match XLA dot: t = fma(r02, z, r00*x); the r01*y term is exactly 0.
        float xr = fmaf(m.y, z, m.x * x);
        float zr = fmaf(m.w, z, m.z * x);
        int px = (int)rintf((xr + 2.0f) * 16.0f);
        float val = __fdiv_rn(zr, 10.0f);   // exact IEEE /10 even under fast-math
        bool in = py_in & (px >= 0) & (px < IMS);
        int pix = in ? (py_off + px) : 0;   // masked points write at (0,0)
        atomicMax(base + (size_t)r * NPIX + pix,
                  tag | (unsigned long long)__float_as_uint(val));
    }
}

__global__ __launch_bounds__(256) void unpack_kernel(float* __restrict__ out)
{
    int i = blockIdx.x * 256 + threadIdx.x;   // [0, TOTPIX)
    unsigned long long k = g_scratch[i];
    g_scratch[i] = 0ULL;                      // reset for the next replay
    out[i] = (k >> 32) ? __uint_as_float((unsigned int)k) : 0.0f;
}

extern "C" void kernel_launch(void* const* d_in, const int* in_sizes, int n_in,
                              void* d_out, int out_size)
{
    const float* xyz = (const float*)d_in[0];   // [32, 16384, 3] f32
    const float* rot = (const float*)d_in[1];   // [24, 3, 3] f32
    float* out = (float*)d_out;                 // [32, 24, 64, 64] f32

    scatter_kernel<<<(BATCH * NPTS) / 256, 256>>>(xyz, rot);
    unpack_kernel<<<TOTPIX / 256, 256>>>(out);
}